// round 14
// baseline (speedup 1.0000x reference)
#include <cuda_runtime.h>

// LoCon1d: out[b][o][s] = sum_{c,k} in[b][c][s+k-1] * w[o][c][s][k] + bias[o][s]
// B=16, Cin=64, Cout=64, S=1024, K=3 (zero pad)
//
//  1) transpose_kernel: input (B,C,S) -> g_trans[c][1+s][b], zero halo rows
//  2) locon1d_kernel:   O_TILE=4 -> 1024 blocks (~7 resident/SM) -> ~7
//                       independent cp.async streams per SM (vs 1.7 before).

#define S_LEN   1024
#define CIN     64
#define COUT    64
#define BATCH   16
#define KW      3
#define S_TILE  16
#define O_TILE  4
#define HALO    (S_TILE + 2)        // 18
#define THREADS 64

// transposed input: [c][j=0..1025][b=0..15], j = s+1 (rows 0 and 1025 zero)
#define TR_J    (S_LEN + 2)
__device__ float g_trans[CIN * TR_J * BATCH];

// ring stage: weight [o][s][k] 4*16*3 f32 = 768B at 0,
//             input 18 rows x 5 f4 (stride-5 pad, 4 used) = 1440B at 768
#define IN_OFF_B     768
#define STAGE_BYTES  2560            // 768 + 1440 = 2208, padded to 128B mult
#define N_STAGES     8
#define SMEM_BYTES   (N_STAGES * STAGE_BYTES)   // 20480

typedef unsigned long long u64;

__device__ __forceinline__ u64 splat2(float w) {
    u64 r;
    asm("mov.b64 %0, {%1, %1};" : "=l"(r) : "f"(w));
    return r;
}
__device__ __forceinline__ void fma2(u64 &d, u64 a, u64 b) {
    asm("fma.rn.f32x2 %0, %1, %2, %0;" : "+l"(d) : "l"(a), "l"(b));
}
__device__ __forceinline__ float2 u2f(u64 u) {
    float2 r;
    asm("mov.b64 {%0, %1}, %2;" : "=f"(r.x), "=f"(r.y) : "l"(u));
    return r;
}
__device__ __forceinline__ void cp16(unsigned dst, const void* src) {
    asm volatile("cp.async.cg.shared.global [%0], [%1], 16;" :: "r"(dst), "l"(src));
}
__device__ __forceinline__ void cp_commit() {
    asm volatile("cp.async.commit_group;");
}
__device__ __forceinline__ void cp_wait6() {
    asm volatile("cp.async.wait_group 6;");
}

// ---------------------------------------------------------------------------
// transpose: input[b][c][s] -> g_trans[c][1+s][b]; zero rows j=0 and j=1025
// ---------------------------------------------------------------------------
__global__ void __launch_bounds__(256)
transpose_kernel(const float* __restrict__ input)
{
    __shared__ float tile[BATCH][65];

    const int c  = blockIdx.x;
    const int s0 = blockIdx.y * 64;
    const int tid = threadIdx.x;

    #pragma unroll
    for (int r = 0; r < 4; ++r) {
        const int idx = tid + r * 256;
        const int b  = idx >> 6;
        const int sl = idx & 63;
        tile[b][sl] = input[((size_t)b * CIN + c) * S_LEN + s0 + sl];
    }
    __syncthreads();

    #pragma unroll
    for (int r = 0; r < 4; ++r) {
        const int idx = tid + r * 256;
        const int b  = idx & 15;
        const int sl = idx >> 4;
        g_trans[((size_t)c * TR_J + 1 + s0 + sl) * BATCH + b] = tile[b][sl];
    }

    if (blockIdx.x == 0 && blockIdx.y == 0) {
        for (int e = tid; e < CIN * BATCH; e += 256) {
            const int cc = e >> 4, bb = e & 15;
            g_trans[((size_t)cc * TR_J + 0) * BATCH + bb]        = 0.f;
            g_trans[((size_t)cc * TR_J + TR_J - 1) * BATCH + bb] = 0.f;
        }
    }
}

// ---------------------------------------------------------------------------
// main conv: 1024 blocks x 64 threads (~7 resident blocks/SM).
// thread: o_l = tid>>4 (0..3, one cout), sl = tid&15 (s = s0+sl), 16 batches.
// ---------------------------------------------------------------------------
__global__ void __launch_bounds__(THREADS, 8)
locon1d_kernel(const float* __restrict__ weight,
               const float* __restrict__ bias,
               float* __restrict__ out)
{
    extern __shared__ char smem[];

    const int s0 = blockIdx.x * S_TILE;
    const int o0 = blockIdx.y * O_TILE;
    const int tid = threadIdx.x;
    const unsigned sh_u = (unsigned)__cvta_generic_to_shared(smem);

    // ---- cp.async fill per stage ------------------------------------------
    // weight: f4 f in [0,48): o = f/12, r = f%12  ([o][s][k] layout)
    // input:  f2 in [0,72): j = f2/4, bq = f2&3 -> f4 slot 5j+bq (stride-5)
    //         f2 = tid (all 64) and f2 = tid+64 (tid<8)
    const float* wsrc = weight + ((size_t)(o0 + tid / 12) * CIN) * (S_LEN * 3)
                               + (size_t)s0 * 3 + (tid % 12) * 4;
    const int ijA = tid >> 2,        ibA = tid & 3;          // f2 = tid
    const int ijB = (tid + 64) >> 2, ibB = tid & 3;          // f2 = tid+64
    const float* isrcA = g_trans + ((size_t)(s0 + ijA)) * BATCH + ibA * 4;
    const float* isrcB = g_trans + ((size_t)(s0 + ijB)) * BATCH + ibB * 4;
    const unsigned idstA = (unsigned)(IN_OFF_B + (5 * ijA + ibA) * 16);
    const unsigned idstB = (unsigned)(IN_OFF_B + (5 * ijB + ibB) * 16);

    auto WISSUE = [&](int c) {
        const unsigned stg = sh_u + (unsigned)((c & (N_STAGES - 1)) * STAGE_BYTES);
        if (tid < 48)
            cp16(stg + (unsigned)(tid * 16), wsrc + (size_t)c * (S_LEN * 3));
        cp16(stg + idstA, isrcA + (size_t)c * (TR_J * BATCH));
        if (tid < 8)
            cp16(stg + idstB, isrcB + (size_t)c * (TR_J * BATCH));
        cp_commit();
    };

    // prologue: 7 stages. Before iter-c wait: commits = 7+c; wait_group 6 ->
    // completed >= c+1 -> group c (stage c) resident. (R9-verified math.)
    WISSUE(0); WISSUE(1); WISSUE(2); WISSUE(3); WISSUE(4); WISSUE(5); WISSUE(6);

    // ---- compute mapping --------------------------------------------------
    const int sl  = tid & 15;           // s = s0 + sl
    const int o_l = tid >> 4;           // 0..3, one cout
    const int o   = o0 + o_l;
    const int s   = s0 + sl;

    u64 acc[8];
    #pragma unroll
    for (int p = 0; p < 8; ++p) acc[p] = 0ull;

    for (int c = 0; c < CIN; ++c) {
        cp_wait6();
        __syncthreads();     // stage c visible; slot (c-1)&7 now free

        // refill first: stage c+7 -> slot (c-1)&7 (disjoint from read slot c&7)
        if (c + 7 < CIN) WISSUE(c + 7); else cp_commit();

        const char* stg = smem + (c & (N_STAGES - 1)) * STAGE_BYTES;

        // weights: [o][s][k] floats; bank = (48*o_l + 3*sl + k) mod 32
        //          = (3*lane + k) mod 32 across the warp -> conflict-free
        const float* wf = reinterpret_cast<const float*>(stg);
        float w[3];
        #pragma unroll
        for (int k = 0; k < KW; ++k)
            w[k] = wf[o_l * 48 + sl * 3 + k];

        // input rows j = sl+k, 4 f4 (8 u64) each; 2-phase LDS.128 + broadcast
        const ulonglong2* vstg =
            reinterpret_cast<const ulonglong2*>(stg + IN_OFF_B);
        ulonglong2 v[3][4];
        #pragma unroll
        for (int k = 0; k < KW; ++k)
            #pragma unroll
            for (int bq = 0; bq < 4; ++bq)
                v[k][bq] = vstg[5 * (sl + k) + bq];

        #pragma unroll
        for (int k = 0; k < KW; ++k) {
            const u64 w2 = splat2(w[k]);
            #pragma unroll
            for (int bq = 0; bq < 4; ++bq) {
                fma2(acc[2 * bq],     v[k][bq].x, w2);
                fma2(acc[2 * bq + 1], v[k][bq].y, w2);
            }
        }
    }

    // ---- epilogue: bias + store ------------------------------------------
    {
        const float bz = bias[(size_t)o * S_LEN + s];
        #pragma unroll
        for (int p = 0; p < 8; ++p) {
            const float2 a = u2f(acc[p]);
            const int b0 = 2 * p;
            out[((size_t)(b0       * COUT + o)) * S_LEN + s] = a.x + bz;
            out[((size_t)((b0 + 1) * COUT + o)) * S_LEN + s] = a.y + bz;
        }
    }
}

extern "C" void kernel_launch(void* const* d_in, const int* in_sizes, int n_in,
                              void* d_out, int out_size) {
    const float* input  = (const float*)d_in[0];
    const float* weight = (const float*)d_in[1];
    const float* bias   = (const float*)d_in[2];
    float* out = (float*)d_out;

    cudaFuncSetAttribute(locon1d_kernel,
                         cudaFuncAttributeMaxDynamicSharedMemorySize, SMEM_BYTES);

    dim3 tgrid(CIN, S_LEN / 64);                 // (64, 16)
    transpose_kernel<<<tgrid, 256>>>(input);

    dim3 grid(S_LEN / S_TILE, COUT / O_TILE);    // (64, 16) = 1024 blocks
    locon1d_kernel<<<grid, THREADS, SMEM_BYTES>>>(weight, bias, out);
}

// round 15
// speedup vs baseline: 1.2495x; 1.2495x over previous
#include <cuda_runtime.h>

// LoCon1d: out[b][o][s] = sum_{c,k} in[b][c][s+k-1] * w[o][c][s][k] + bias[o][s]
// B=16, Cin=64, Cout=64, S=1024, K=3 (zero pad)
//
//  1) transpose_kernel: input (B,C,S) -> g_trans[c][1+s][b], zero halo rows
//  2) locon1d_kernel:   S_TILE=64, O_TILE=4 -> weight DRAM runs of 768B
//                       (vs 192B before) to raise DRAM efficiency.

#define S_LEN   1024
#define CIN     64
#define COUT    64
#define BATCH   16
#define KW      3
#define S_TILE  64
#define O_TILE  4
#define THREADS 256

// transposed input: [c][j=0..1025][b=0..15], j = s+1 (rows 0 and 1025 zero)
#define TR_J    (S_LEN + 2)
__device__ float g_trans[CIN * TR_J * BATCH];

// ring stage:
//   weight: 4 o-slices, each 64s*3k f32 = 768B padded to 800B (bank-conflict-
//           free scalar LDS: (8*o + 3*sl3 + k) mod 32 all distinct) -> 3200B
//   input:  66 rows (j = s_loc+k, s_loc<64) x 5 f4 (stride-5, 4 used) = 5280B
#define W_OSTRIDE_B  800
#define IN_OFF_B     3200
#define STAGE_BYTES  8576            // 3200 + 5280 = 8480 -> 67*128
#define N_STAGES     8
#define SMEM_BYTES   (N_STAGES * STAGE_BYTES)   // 68608

typedef unsigned long long u64;

__device__ __forceinline__ u64 splat2(float w) {
    u64 r;
    asm("mov.b64 %0, {%1, %1};" : "=l"(r) : "f"(w));
    return r;
}
__device__ __forceinline__ void fma2(u64 &d, u64 a, u64 b) {
    asm("fma.rn.f32x2 %0, %1, %2, %0;" : "+l"(d) : "l"(a), "l"(b));
}
__device__ __forceinline__ float2 u2f(u64 u) {
    float2 r;
    asm("mov.b64 {%0, %1}, %2;" : "=f"(r.x), "=f"(r.y) : "l"(u));
    return r;
}
__device__ __forceinline__ void cp16(unsigned dst, const void* src) {
    asm volatile("cp.async.cg.shared.global [%0], [%1], 16;" :: "r"(dst), "l"(src));
}
__device__ __forceinline__ void cp_commit() {
    asm volatile("cp.async.commit_group;");
}
__device__ __forceinline__ void cp_wait6() {
    asm volatile("cp.async.wait_group 6;");
}

// ---------------------------------------------------------------------------
// transpose: input[b][c][s] -> g_trans[c][1+s][b]; zero rows j=0 and j=1025
// ---------------------------------------------------------------------------
__global__ void __launch_bounds__(256)
transpose_kernel(const float* __restrict__ input)
{
    __shared__ float tile[BATCH][65];

    const int c  = blockIdx.x;
    const int s0 = blockIdx.y * 64;
    const int tid = threadIdx.x;

    #pragma unroll
    for (int r = 0; r < 4; ++r) {
        const int idx = tid + r * 256;
        const int b  = idx >> 6;
        const int sl = idx & 63;
        tile[b][sl] = input[((size_t)b * CIN + c) * S_LEN + s0 + sl];
    }
    __syncthreads();

    #pragma unroll
    for (int r = 0; r < 4; ++r) {
        const int idx = tid + r * 256;
        const int b  = idx & 15;
        const int sl = idx >> 4;
        g_trans[((size_t)c * TR_J + 1 + s0 + sl) * BATCH + b] = tile[b][sl];
    }

    if (blockIdx.x == 0 && blockIdx.y == 0) {
        for (int e = tid; e < CIN * BATCH; e += 256) {
            const int cc = e >> 4, bb = e & 15;
            g_trans[((size_t)cc * TR_J + 0) * BATCH + bb]        = 0.f;
            g_trans[((size_t)cc * TR_J + TR_J - 1) * BATCH + bb] = 0.f;
        }
    }
}

// ---------------------------------------------------------------------------
// main conv: grid (16 s-tiles, 16 o-tiles) = 256 blocks x 256 threads.
// warp w: s_loc = 8w + (lane>>2), o_l = lane&3; thread owns 16 batches.
// ---------------------------------------------------------------------------
__global__ void __launch_bounds__(THREADS, 2)
locon1d_kernel(const float* __restrict__ weight,
               const float* __restrict__ bias,
               float* __restrict__ out)
{
    extern __shared__ char smem[];

    const int s0 = blockIdx.x * S_TILE;
    const int o0 = blockIdx.y * O_TILE;
    const int tid = threadIdx.x;
    const unsigned sh_u = (unsigned)__cvta_generic_to_shared(smem);

    // ---- cp.async fill per stage ------------------------------------------
    // weight: tid<192: o = tid/48, r = tid%48 -> 768B contiguous run per (o,c)
    const int wo = tid / 48, wr = tid % 48;
    const float* wsrc = weight + ((size_t)(o0 + wo) * CIN) * (S_LEN * 3)
                               + (size_t)s0 * 3 + wr * 4;
    const unsigned wdst_off = (unsigned)(wo * W_OSTRIDE_B + wr * 16);
    // input: f2 t in [0,264): j = t>>2, bq = t&3 -> f4 slot 5j+bq
    const int ijA = tid >> 2,          ibA = tid & 3;          // t = tid (all)
    const int ijB = (tid + 256) >> 2,  ibB = tid & 3;          // t = tid+256
    const float* isrcA = g_trans + ((size_t)(s0 + ijA)) * BATCH + ibA * 4;
    const float* isrcB = g_trans + ((size_t)(s0 + ijB)) * BATCH + ibB * 4;
    const unsigned idstA = (unsigned)(IN_OFF_B + (5 * ijA + ibA) * 16);
    const unsigned idstB = (unsigned)(IN_OFF_B + (5 * ijB + ibB) * 16);

    auto WISSUE = [&](int c) {
        const unsigned stg = sh_u + (unsigned)((c & (N_STAGES - 1)) * STAGE_BYTES);
        if (tid < 192)
            cp16(stg + wdst_off, wsrc + (size_t)c * (S_LEN * 3));
        cp16(stg + idstA, isrcA + (size_t)c * (TR_J * BATCH));
        if (tid < 8)
            cp16(stg + idstB, isrcB + (size_t)c * (TR_J * BATCH));
        cp_commit();
    };

    // prologue: 7 stages. Before iter-c wait: commits = 7+c; wait_group 6 ->
    // completed >= c+1 -> group c (stage c) resident. (R9-verified math.)
    WISSUE(0); WISSUE(1); WISSUE(2); WISSUE(3); WISSUE(4); WISSUE(5); WISSUE(6);

    // ---- compute mapping --------------------------------------------------
    const int lane = tid & 31;
    const int wrp  = tid >> 5;
    const int o_l  = lane & 3;
    const int sl3  = lane >> 2;          // 0..7
    const int s_loc = wrp * 8 + sl3;     // 0..63
    const int o = o0 + o_l;
    const int s = s0 + s_loc;

    u64 acc[8];
    #pragma unroll
    for (int p = 0; p < 8; ++p) acc[p] = 0ull;

    for (int c = 0; c < CIN; ++c) {
        cp_wait6();
        __syncthreads();     // stage c visible; slot (c-1)&7 now free

        // refill first: stage c+7 -> slot (c-1)&7 (disjoint from read slot c&7)
        if (c + 7 < CIN) WISSUE(c + 7); else cp_commit();

        const char* stg = smem + (c & (N_STAGES - 1)) * STAGE_BYTES;

        // weights: o-slice stride 200 f32 -> bank (8*o_l + 3*s_loc + k) mod 32,
        // distinct across the warp -> conflict-free scalar LDS
        const float* wfl = reinterpret_cast<const float*>(stg);
        float w[3];
        #pragma unroll
        for (int k = 0; k < KW; ++k)
            w[k] = wfl[o_l * (W_OSTRIDE_B / 4) + s_loc * 3 + k];

        // input rows j = s_loc+k, 4 f4 each; same-row lanes (4 o_l) broadcast,
        // 8 distinct rows per warp at stride 5 -> 1-phase LDS.128
        const ulonglong2* vstg =
            reinterpret_cast<const ulonglong2*>(stg + IN_OFF_B);
        ulonglong2 v[3][4];
        #pragma unroll
        for (int k = 0; k < KW; ++k)
            #pragma unroll
            for (int bq = 0; bq < 4; ++bq)
                v[k][bq] = vstg[5 * (s_loc + k) + bq];

        #pragma unroll
        for (int k = 0; k < KW; ++k) {
            const u64 w2 = splat2(w[k]);
            #pragma unroll
            for (int bq = 0; bq < 4; ++bq) {
                fma2(acc[2 * bq],     v[k][bq].x, w2);
                fma2(acc[2 * bq + 1], v[k][bq].y, w2);
            }
        }
    }

    // ---- epilogue: bias + store ------------------------------------------
    {
        const float bz = bias[(size_t)o * S_LEN + s];
        #pragma unroll
        for (int p = 0; p < 8; ++p) {
            const float2 a = u2f(acc[p]);
            const int b0 = 2 * p;
            out[((size_t)(b0       * COUT + o)) * S_LEN + s] = a.x + bz;
            out[((size_t)((b0 + 1) * COUT + o)) * S_LEN + s] = a.y + bz;
        }
    }
}

extern "C" void kernel_launch(void* const* d_in, const int* in_sizes, int n_in,
                              void* d_out, int out_size) {
    const float* input  = (const float*)d_in[0];
    const float* weight = (const float*)d_in[1];
    const float* bias   = (const float*)d_in[2];
    float* out = (float*)d_out;

    cudaFuncSetAttribute(locon1d_kernel,
                         cudaFuncAttributeMaxDynamicSharedMemorySize, SMEM_BYTES);

    dim3 tgrid(CIN, S_LEN / 64);                 // (64, 16)
    transpose_kernel<<<tgrid, 256>>>(input);

    dim3 grid(S_LEN / S_TILE, COUT / O_TILE);    // (16, 16) = 256 blocks
    locon1d_kernel<<<grid, THREADS, SMEM_BYTES>>>(weight, bias, out);
}